// round 4
// baseline (speedup 1.0000x reference)
#include <cuda_runtime.h>
#include <cstdint>

// ---------------- problem constants ----------------
#define NB     2048
#define F0V    39
#define DDIM   16
#define P0     1521
#define P1     4992

// chunk schedule: 6 passes x 39 f-chunks
//  pass 0: layer1, q-window [0,32),  Kc=32
//  pass 1: layer1, q-window [32,40), Kc=8  (q=39 zero-padded)
//  pass 2-5: layer2, q-window [32w,32w+32), Kc=32
#define NPASS  6
#define NF     39
#define NCHUNK (NPASS * NF)      // 234
#define CS_BIG 4096              // floats per Kc=32 W chunk (128n x 32k)
#define CS_SM  1024              // floats per Kc=8 chunk
#define WP_TOTAL (NF * CS_BIG * 5 + NF * CS_SM)   // 838656 floats

// ---------------- smem layout (bytes) ----------------
#define OFF_X    0               // 128 x 40 fp32 = 20480
#define OFF_H1   20480           // 128 x 132 fp32 = 67584
#define OFF_B    88064           // 2 x 16384 W buffers
#define SMEM_TOTAL (OFF_B + 2 * 16384)   // 120832

__device__ float g_Wp[WP_TOTAL];

// ---------------- helpers ----------------
__device__ __forceinline__ uint32_t smem_u32(const void* p) {
    uint32_t a;
    asm("{ .reg .u64 t; cvta.to.shared.u64 t, %1; cvt.u32.u64 %0, t; }" : "=r"(a) : "l"(p));
    return a;
}
__device__ __forceinline__ uint32_t f2tf(float x) {
    uint32_t r;
    asm("cvt.rna.tf32.f32 %0, %1;" : "=r"(r) : "f"(x));
    return r;
}
__device__ __forceinline__ void mma_tf32(float* c, const uint32_t* a, uint32_t b0, uint32_t b1) {
    asm volatile(
        "mma.sync.aligned.m16n8k8.row.col.f32.tf32.tf32.f32 "
        "{%0,%1,%2,%3},{%4,%5,%6,%7},{%8,%9},{%0,%1,%2,%3};"
        : "+f"(c[0]), "+f"(c[1]), "+f"(c[2]), "+f"(c[3])
        : "r"(a[0]), "r"(a[1]), "r"(a[2]), "r"(a[3]), "r"(b0), "r"(b1));
}

__device__ __forceinline__ int pass_base(int p) {
    if (p == 0) return 0;
    if (p == 1) return NF * CS_BIG;
    return NF * CS_BIG + NF * CS_SM + (p - 2) * NF * CS_BIG;
}

// ---------------- prepass: W -> tf32 fragment-packed layout ----------------
// Kc=32 chunk layout: float4[nbg(16)][ks2(2)][lane(32)]:
//   .x=b0(ks=2ks2) .y=b1(ks=2ks2) .z=b0(ks=2ks2+1) .w=b1(ks=2ks2+1)
//   b0: k = 8*ks + lane%4 ; b1: k = 8*ks + lane%4 + 4 ; n = nbg*8 + lane/4
// Kc=8 chunk layout: float2[nbg(16)][lane(32)] = {b0, b1}
__global__ void prep_kernel(const float* __restrict__ W0, const float* __restrict__ W1) {
    for (int idx = blockIdx.x * blockDim.x + threadIdx.x; idx < WP_TOTAL;
         idx += gridDim.x * blockDim.x) {
        int p, rem;
        if (idx < NF * CS_BIG) { p = 0; rem = idx; }
        else if (idx < NF * CS_BIG + NF * CS_SM) { p = 1; rem = idx - NF * CS_BIG; }
        else {
            int j = idx - (NF * CS_BIG + NF * CS_SM);
            p = 2 + j / (NF * CS_BIG);
            rem = j % (NF * CS_BIG);
        }
        int cs = (p == 1) ? CS_SM : CS_BIG;
        int f = rem / cs, r = rem - f * cs;
        int n, kl;
        if (p == 1) {
            int q2 = r >> 1, comp = r & 1;
            int lane = q2 & 31, nbg = q2 >> 5;
            kl = comp * 4 + (lane & 3);
            n = nbg * 8 + (lane >> 2);
        } else {
            int q4 = r >> 2, comp = r & 3;
            int lane = q4 & 31, ks2 = (q4 >> 5) & 1, nbg = q4 >> 6;
            kl = ks2 * 16 + comp * 4 + (lane & 3);
            n = nbg * 8 + (lane >> 2);
        }
        float v;
        if (p == 0) {
            v = W0[n * P0 + f * F0V + kl];                 // q = kl < 32 < 39
        } else if (p == 1) {
            int q = 32 + kl;
            v = (q < F0V) ? W0[n * P0 + f * F0V + q] : 0.0f;
        } else {
            int q = 32 * (p - 2) + kl;
            v = W1[n * P1 + f * 128 + q];
        }
        g_Wp[idx] = __uint_as_float(f2tf(v));
    }
}

// ---------------- cp.async W prefetch ----------------
__device__ __forceinline__ void prefetch_chunk(int c, uint32_t wsm, int tid) {
    int p = c / NF, f = c - p * NF;
    int cs = (p == 1) ? CS_SM : CS_BIG;
    const float* g = g_Wp + pass_base(p) + f * cs + tid * 4;
    uint32_t dst = wsm + (c & 1) * 16384 + tid * 16;
    int n16 = cs >> 10;   // 4 (Kc=32) or 1 (Kc=8) iterations of 256thr x 16B
    #pragma unroll
    for (int i = 0; i < 4; ++i)
        if (i < n16)
            asm volatile("cp.async.cg.shared.global [%0], [%1], 16;"
                         :: "r"(dst + i * 4096), "l"(g + i * 1024) : "memory");
    asm volatile("cp.async.commit_group;" ::: "memory");
}

// ---------------- epilogue helpers ----------------
__device__ __forceinline__ void store_acc(float* H1s, const float acc[4][4][4],
                                          int mb, int nbb, int tq, int tr) {
    #pragma unroll
    for (int mf = 0; mf < 4; ++mf)
        #pragma unroll
        for (int nb = 0; nb < 4; ++nb) {
            int r0 = mb + mf * 16 + tq;
            int col = nbb + nb * 8 + tr * 2;
            *reinterpret_cast<float2*>(&H1s[r0 * 132 + col]) =
                make_float2(acc[mf][nb][0], acc[mf][nb][1]);
            *reinterpret_cast<float2*>(&H1s[(r0 + 8) * 132 + col]) =
                make_float2(acc[mf][nb][2], acc[mf][nb][3]);
        }
}

__device__ __forceinline__ void write_out(float* __restrict__ out, const float* H1s,
                                          int b0, int colbase, int tid) {
    #pragma unroll
    for (int i = 0; i < 4; ++i) {
        int idx = tid + i * 256;          // 0..1023
        int bl = idx >> 7, h = idx & 127;
        float s = 0.0f;
        #pragma unroll
        for (int d = 0; d < 16; ++d) s += H1s[(bl * 16 + d) * 132 + h];
        out[(size_t)(b0 + bl) * 256 + colbase + h] = s;
    }
}

// ---------------- main kernel ----------------
// 256 CTAs, M=128 rows (8 batches x 16 d) per CTA, N=128 (HOUT).
// 8 warps as 2(m)x4(n): warp tile 64x32.
__global__ __launch_bounds__(256, 1)
void cin_kernel(const float* __restrict__ x, float* __restrict__ out) {
    extern __shared__ char smem[];
    float* Xs  = reinterpret_cast<float*>(smem + OFF_X);    // [128][40], col 39 = 0
    float* H1s = reinterpret_cast<float*>(smem + OFF_H1);   // [128][132]
    char*  wbuf = smem + OFF_B;
    const uint32_t wsm = smem_u32(wbuf);

    const int tid = threadIdx.x;
    const int lane = tid & 31, w = tid >> 5;
    const int tq = lane >> 2, tr = lane & 3;
    const int wm = w & 1, wn = w >> 1;
    const int mb = wm * 64, nbb = wn * 32;

    // ---- load x tile: row bd = b_loc*16 + d, col f ----
    const int b0 = blockIdx.x * 8;
    const float* xg = x + (size_t)b0 * (F0V * DDIM);
    for (int idx = tid; idx < F0V * 128; idx += 256) {
        int f = idx >> 7, row = idx & 127;
        Xs[row * 40 + f] = xg[(row >> 4) * (F0V * DDIM) + f * DDIM + (row & 15)];
    }
    if (tid < 128) Xs[tid * 40 + 39] = 0.0f;
    __syncthreads();

    float acc[4][4][4];
    #pragma unroll
    for (int a = 0; a < 4; ++a)
        #pragma unroll
        for (int b = 0; b < 4; ++b)
            #pragma unroll
            for (int e = 0; e < 4; ++e) acc[a][b][e] = 0.0f;

    float hf[4][4][4];   // [mfrag][kstep][elem] h-window fragments (fp32)

    prefetch_chunk(0, wsm, tid);
    int c = 0;

    for (int p = 0; p < NPASS; ++p) {
        const float* src = (p < 2) ? Xs : H1s;
        const int stride = (p < 2) ? 40 : 132;
        const int qb = (p == 0) ? 0 : ((p == 1) ? 32 : 32 * (p - 2));
        const int nks = (p == 1) ? 1 : 4;

        // load h-window fragments (reused across all 39 f-chunks of the pass)
        #pragma unroll
        for (int mf = 0; mf < 4; ++mf)
            #pragma unroll
            for (int ks = 0; ks < 4; ++ks)
                if (ks < nks)
                    #pragma unroll
                    for (int e = 0; e < 4; ++e)
                        hf[mf][ks][e] =
                            src[(mb + mf * 16 + tq + 8 * (e & 1)) * stride +
                                qb + ks * 8 + tr + 4 * (e >> 1)];

        for (int f = 0; f < NF; ++f) {
            asm volatile("cp.async.wait_group 0;" ::: "memory");
            __syncthreads();
            if (c + 1 < NCHUNK) prefetch_chunk(c + 1, wsm, tid);

            const char* bp = wbuf + (c & 1) * 16384;

            // a_f = x0[row][f] for this warp's 8 rows
            float af0[4], af1[4];
            #pragma unroll
            for (int mf = 0; mf < 4; ++mf) {
                af0[mf] = Xs[(mb + mf * 16 + tq) * 40 + f];
                af1[mf] = Xs[(mb + mf * 16 + tq + 8) * 40 + f];
            }

            if (p != 1) {
                const float4* bt = reinterpret_cast<const float4*>(bp);
                #pragma unroll
                for (int ks2 = 0; ks2 < 2; ++ks2) {
                    float4 bv[4];
                    #pragma unroll
                    for (int nb = 0; nb < 4; ++nb)
                        bv[nb] = bt[((wn * 4 + nb) * 2 + ks2) * 32 + lane];
                    #pragma unroll
                    for (int h2 = 0; h2 < 2; ++h2) {
                        const int ks = ks2 * 2 + h2;
                        uint32_t a[4][4];
                        #pragma unroll
                        for (int mf = 0; mf < 4; ++mf) {
                            a[mf][0] = f2tf(af0[mf] * hf[mf][ks][0]);
                            a[mf][1] = f2tf(af1[mf] * hf[mf][ks][1]);
                            a[mf][2] = f2tf(af0[mf] * hf[mf][ks][2]);
                            a[mf][3] = f2tf(af1[mf] * hf[mf][ks][3]);
                        }
                        #pragma unroll
                        for (int mf = 0; mf < 4; ++mf)
                            #pragma unroll
                            for (int nb = 0; nb < 4; ++nb)
                                mma_tf32(acc[mf][nb], a[mf],
                                         h2 ? __float_as_uint(bv[nb].z) : __float_as_uint(bv[nb].x),
                                         h2 ? __float_as_uint(bv[nb].w) : __float_as_uint(bv[nb].y));
                    }
                }
            } else {
                const float2* bt = reinterpret_cast<const float2*>(bp);
                float2 bv[4];
                #pragma unroll
                for (int nb = 0; nb < 4; ++nb)
                    bv[nb] = bt[(wn * 4 + nb) * 32 + lane];
                uint32_t a[4][4];
                #pragma unroll
                for (int mf = 0; mf < 4; ++mf) {
                    a[mf][0] = f2tf(af0[mf] * hf[mf][0][0]);
                    a[mf][1] = f2tf(af1[mf] * hf[mf][0][1]);
                    a[mf][2] = f2tf(af0[mf] * hf[mf][0][2]);
                    a[mf][3] = f2tf(af1[mf] * hf[mf][0][3]);
                }
                #pragma unroll
                for (int mf = 0; mf < 4; ++mf)
                    #pragma unroll
                    for (int nb = 0; nb < 4; ++nb)
                        mma_tf32(acc[mf][nb], a[mf],
                                 __float_as_uint(bv[nb].x), __float_as_uint(bv[nb].y));
            }
            ++c;
        }

        if (p == 1) {
            // layer-1 done: D1 -> H1s, emit layer-1 output, reset acc
            __syncthreads();
            store_acc(H1s, acc, mb, nbb, tq, tr);
            __syncthreads();
            write_out(out, H1s, b0, 0, tid);
            #pragma unroll
            for (int a = 0; a < 4; ++a)
                #pragma unroll
                for (int b = 0; b < 4; ++b)
                    #pragma unroll
                    for (int e = 0; e < 4; ++e) acc[a][b][e] = 0.0f;
        }
    }

    // layer-2 epilogue
    __syncthreads();
    store_acc(H1s, acc, mb, nbb, tq, tr);
    __syncthreads();
    write_out(out, H1s, b0, 128, tid);
}

// ---------------- launch ----------------
extern "C" void kernel_launch(void* const* d_in, const int* in_sizes, int n_in,
                              void* d_out, int out_size) {
    const float* x = nullptr;
    const float* W0 = nullptr;
    const float* W1 = nullptr;
    for (int i = 0; i < n_in; ++i) {
        if (in_sizes[i] == NB * F0V * DDIM)  x  = (const float*)d_in[i];
        else if (in_sizes[i] == 128 * P0)    W0 = (const float*)d_in[i];
        else if (in_sizes[i] == 128 * P1)    W1 = (const float*)d_in[i];
    }
    prep_kernel<<<512, 256>>>(W0, W1);
    cudaFuncSetAttribute(cin_kernel, cudaFuncAttributeMaxDynamicSharedMemorySize, SMEM_TOTAL);
    cin_kernel<<<256, 256, SMEM_TOTAL>>>(x, (float*)d_out);
}